// round 1
// baseline (speedup 1.0000x reference)
#include <cuda_runtime.h>

#define BB 4
#define HH 128
#define WW 128
#define HW (HH*WW)

typedef unsigned long long ull;

// ---------------- scratch (device globals; no runtime allocation) ----------------
__device__ float g_flow_up[BB*2*HW];      // 0.5 MB
__device__ float g_f2w[BB*128*HW];        // 33.5 MB
__device__ float g_corr[BB*49*HW];        // 12.8 MB
__device__ float g_h1[BB*128*HW];         // 33.5 MB
__device__ float g_h2[BB*64*HW];          // 16.8 MB
__device__ float g_h3[BB*32*HW];          // 8.4 MB

// ---------------- packed f32x2 helpers ----------------
__device__ __forceinline__ ull ffma2(ull a, ull b, ull c) {
    ull d;
    asm("fma.rn.f32x2 %0, %1, %2, %3;" : "=l"(d) : "l"(a), "l"(b), "l"(c));
    return d;
}
__device__ __forceinline__ ull pack2(float lo, float hi) {
    ull r;
    asm("mov.b64 %0, {%1, %2};" : "=l"(r) : "f"(lo), "f"(hi));
    return r;
}
__device__ __forceinline__ float2 unpack2(ull v) {
    float2 r;
    asm("mov.b64 {%0, %1}, %2;" : "=f"(r.x), "=f"(r.y) : "l"(v));
    return r;
}

// ---------------- 1) grouped ConvTranspose2d(2,2,k=4,s=2,p=1,groups=2) ----------------
// out[b,g,y,x] = sum over (i,j): in[b,g,i,j] * w[g,0,ky,kx]  where ky=y+1-2i, kx=x+1-2j in [0,4)
__global__ void k_upsample(const float* __restrict__ flow, const float* __restrict__ up_w,
                           float* __restrict__ out) {
    int idx = blockIdx.x * blockDim.x + threadIdx.x;
    if (idx >= BB*2*HW) return;
    int x = idx & 127;
    int y = (idx >> 7) & 127;
    int g = (idx >> 14) & 1;
    int b = idx >> 15;
    const float* fin = flow + (b*2 + g) * 64 * 64;
    const float* wg  = up_w + g * 16;
    float acc = 0.f;
    #pragma unroll
    for (int ky = 0; ky < 4; ky++) {
        int t = y + 1 - ky;
        if (t & 1) continue;
        int i = t >> 1;
        if ((unsigned)i >= 64u) continue;
        #pragma unroll
        for (int kx = 0; kx < 4; kx++) {
            int s = x + 1 - kx;
            if (s & 1) continue;
            int j = s >> 1;
            if ((unsigned)j >= 64u) continue;
            acc += fin[i*64 + j] * wg[ky*4 + kx];
        }
    }
    out[idx] = acc;
}

// ---------------- 2) warp feature2 (bilinear, reflect border, align_corners) ----------------
__device__ __forceinline__ float reflectf(float v, float n) {
    float t = fmodf(fabsf(v), 2.0f * n);
    return n - fabsf(t - n);
}

__global__ void k_warp(const float* __restrict__ f2, const float* __restrict__ fu,
                       float* __restrict__ f2w) {
    int x = threadIdx.x;        // 0..127
    int y = blockIdx.x;         // 0..127
    int b = blockIdx.y;         // 0..3
    int c0 = blockIdx.z * 32;   // channel chunk

    const float* fub = fu + (size_t)b*2*HW;
    float u0 = fub[y*WW + x];          // flow_up channel 0 -> y displacement
    float u1 = fub[HW + y*WW + x];     // flow_up channel 1 -> x displacement

    // project with dt = -DT_EFF = -0.05 reduces to pixel-space +0.05*u
    float fx = reflectf((float)x + 0.05f*u1, 127.f);
    float fy = reflectf((float)y + 0.05f*u0, 127.f);

    float x0f = floorf(fx), y0f = floorf(fy);
    float wx = fx - x0f, wy = fy - y0f;
    int x0 = min(max((int)x0f, 0), 127);
    int x1 = min(x0 + 1, 127);
    int y0 = min(max((int)y0f, 0), 127);
    int y1 = min(y0 + 1, 127);
    float w00 = (1.f-wx)*(1.f-wy), w01 = wx*(1.f-wy);
    float w10 = (1.f-wx)*wy,       w11 = wx*wy;

    int o00 = y0*WW + x0, o01 = y0*WW + x1, o10 = y1*WW + x0, o11 = y1*WW + x1;
    const float* fb = f2  + (size_t)b*128*HW;
    float*       ob = f2w + (size_t)b*128*HW;
    int po = y*WW + x;
    #pragma unroll 4
    for (int c = c0; c < c0 + 32; c++) {
        const float* fc = fb + (size_t)c*HW;
        ob[(size_t)c*HW + po] = w00*fc[o00] + w01*fc[o01] + w10*fc[o10] + w11*fc[o11];
    }
}

// ---------------- 3) 49-ch cost volume (7x7 window) + leaky(0.01) ----------------
__global__ void __launch_bounds__(256) k_corr(const float* __restrict__ f1,
                                              const float* __restrict__ f2w,
                                              float* __restrict__ corr) {
    __shared__ float s1[16][16];
    __shared__ float s2[22][24];   // 22x22 tile, row padded to 24
    int tx = threadIdx.x, ty = threadIdx.y;
    int tid = ty*16 + tx;
    int bx = blockIdx.x*16, by = blockIdx.y*16, b = blockIdx.z;
    int x = bx + tx, y = by + ty;

    float acc[49];
    #pragma unroll
    for (int d = 0; d < 49; d++) acc[d] = 0.f;

    const float* f1b = f1  + (size_t)b*128*HW;
    const float* f2b = f2w + (size_t)b*128*HW;

    for (int c = 0; c < 128; c++) {
        __syncthreads();
        s1[ty][tx] = f1b[(size_t)c*HW + y*WW + x];
        #pragma unroll
        for (int i = tid; i < 22*22; i += 256) {
            int r = i / 22, col = i - r*22;
            int gy = by - 3 + r, gx = bx - 3 + col;
            float v = 0.f;
            if ((unsigned)gy < (unsigned)HH && (unsigned)gx < (unsigned)WW)
                v = f2b[(size_t)c*HW + gy*WW + gx];
            s2[r][col] = v;
        }
        __syncthreads();
        float a = s1[ty][tx];
        #pragma unroll
        for (int dy = 0; dy < 7; dy++) {
            #pragma unroll
            for (int dx = 0; dx < 7; dx++)
                acc[dy*7 + dx] += a * s2[ty + dy][tx + dx];
        }
    }

    float* cb = corr + (size_t)b*49*HW;
    #pragma unroll
    for (int d = 0; d < 49; d++) {
        float v = acc[d] * (1.f/128.f);
        cb[(size_t)d*HW + y*WW + x] = (v >= 0.f) ? v : 0.01f*v;
    }
}

// ---------------- 4) direct 3x3 conv, pad=1, fused bias+leaky (+optional residual) ----------
// Tile: 32x16 output pixels. Block (16,16): each thread owns a horizontal pixel PAIR
// packed in f32x2 and accumulates KOC output channels. Weights duplicated into both
// lanes in smem; packed FMA doubles fp32 throughput vs scalar FFMA (rt gap on sm_100a).
template<int CIN, int COUT, int KOC>
__global__ void __launch_bounds__(256) k_conv(
    const float* __restrict__ in, const float* __restrict__ w,
    const float* __restrict__ bias, float* __restrict__ out,
    float slope, const float* __restrict__ addsrc)
{
    __shared__ __align__(16) float s_in[18][34];
    __shared__ ull s_wd[KOC*9];

    int tx = threadIdx.x, ty = threadIdx.y;
    int tid = ty*16 + tx;
    int bx = blockIdx.x*32, by = blockIdx.y*16;
    int ocg = blockIdx.z % (COUT / KOC);
    int b   = blockIdx.z / (COUT / KOC);
    int oc0 = ocg * KOC;

    const float* inb = in + (size_t)b*CIN*HW;

    ull acc[KOC];
    #pragma unroll
    for (int o = 0; o < KOC; o++) acc[o] = 0ull;

    for (int c = 0; c < CIN; c++) {
        __syncthreads();
        // load (18 x 34) input halo tile, zero-padded
        #pragma unroll
        for (int i = tid; i < 18*34; i += 256) {
            int r = i / 34, col = i - r*34;
            int gy = by - 1 + r, gx = bx - 1 + col;
            float v = 0.f;
            if ((unsigned)gy < (unsigned)HH && (unsigned)gx < (unsigned)WW)
                v = inb[(size_t)c*HW + gy*WW + gx];
            s_in[r][col] = v;
        }
        // load 3x3 weights for KOC output channels, lane-duplicated
        if (tid < KOC*9) {
            float wv = w[((size_t)(oc0 + tid/9)*CIN + c)*9 + (tid % 9)];
            s_wd[tid] = pack2(wv, wv);
        }
        __syncthreads();

        // build the 9 packed input-pair taps for this pixel pair
        ull P[9];
        #pragma unroll
        for (int ky = 0; ky < 3; ky++) {
            const ull* row = (const ull*)s_in[ty + ky];   // rows are 8B-aligned (136B stride)
            ull A = row[tx];        // (v0, v1)
            ull Bv = row[tx + 1];   // (v2, v3)
            float2 a = unpack2(A), bb = unpack2(Bv);
            P[ky*3 + 0] = A;
            P[ky*3 + 1] = pack2(a.y, bb.x);
            P[ky*3 + 2] = Bv;
        }
        #pragma unroll
        for (int o = 0; o < KOC; o++) {
            #pragma unroll
            for (int t = 0; t < 9; t++)
                acc[o] = ffma2(P[t], s_wd[o*9 + t], acc[o]);
        }
    }

    int y = by + ty;
    int x = bx + 2*tx;
    #pragma unroll
    for (int o = 0; o < KOC; o++) {
        float2 v = unpack2(acc[o]);
        float bv = bias[oc0 + o];
        v.x += bv; v.y += bv;
        v.x = (v.x >= 0.f) ? v.x : slope*v.x;
        v.y = (v.y >= 0.f) ? v.y : slope*v.y;
        size_t off = ((size_t)(b*COUT + oc0 + o))*HW + y*WW + x;
        if (addsrc) { v.x += addsrc[off]; v.y += addsrc[off + 1]; }
        out[off]     = v.x;
        out[off + 1] = v.y;
    }
}

// ---------------- launch ----------------
extern "C" void kernel_launch(void* const* d_in, const int* in_sizes, int n_in,
                              void* d_out, int out_size) {
    const float* feature1 = (const float*)d_in[0];
    const float* feature2 = (const float*)d_in[1];
    const float* flow     = (const float*)d_in[2];
    const float* up_w     = (const float*)d_in[3];
    const float* w1 = (const float*)d_in[4];  const float* b1 = (const float*)d_in[5];
    const float* w2 = (const float*)d_in[6];  const float* b2 = (const float*)d_in[7];
    const float* w3 = (const float*)d_in[8];  const float* b3 = (const float*)d_in[9];
    const float* w4 = (const float*)d_in[10]; const float* b4 = (const float*)d_in[11];
    float* out = (float*)d_out;

    float *p_flow_up, *p_f2w, *p_corr, *p_h1, *p_h2, *p_h3;
    cudaGetSymbolAddress((void**)&p_flow_up, g_flow_up);
    cudaGetSymbolAddress((void**)&p_f2w,     g_f2w);
    cudaGetSymbolAddress((void**)&p_corr,    g_corr);
    cudaGetSymbolAddress((void**)&p_h1,      g_h1);
    cudaGetSymbolAddress((void**)&p_h2,      g_h2);
    cudaGetSymbolAddress((void**)&p_h3,      g_h3);

    k_upsample<<<(BB*2*HW + 255)/256, 256>>>(flow, up_w, p_flow_up);
    k_warp<<<dim3(HH, BB, 4), 128>>>(feature2, p_flow_up, p_f2w);
    k_corr<<<dim3(8, 8, BB), dim3(16, 16)>>>(feature1, p_f2w, p_corr);
    k_conv<49, 128, 8><<<dim3(4, 8, BB*16), dim3(16, 16)>>>(p_corr, w1, b1, p_h1, 0.1f, nullptr);
    k_conv<128, 64, 8><<<dim3(4, 8, BB*8),  dim3(16, 16)>>>(p_h1,  w2, b2, p_h2, 0.1f, nullptr);
    k_conv<64, 32, 8><<<dim3(4, 8, BB*4),  dim3(16, 16)>>>(p_h2,  w3, b3, p_h3, 0.1f, nullptr);
    k_conv<32, 2, 2><<<dim3(4, 8, BB),     dim3(16, 16)>>>(p_h3,  w4, b4, out, 1.0f, p_flow_up);
}

// round 2
// speedup vs baseline: 1.0908x; 1.0908x over previous
#include <cuda_runtime.h>

#define BB 4
#define HH 128
#define WW 128
#define HW (HH*WW)

typedef unsigned long long ull;

// ---------------- scratch (device globals; no runtime allocation) ----------------
__device__ float g_flow_up[BB*2*HW];
__device__ float g_f2w[BB*128*HW];
__device__ float g_corr[BB*49*HW];
__device__ float g_h1[BB*128*HW];
__device__ float g_h2[BB*64*HW];
__device__ float g_h3[BB*32*HW];

// ---------------- packed f32x2 helpers ----------------
__device__ __forceinline__ ull ffma2(ull a, ull b, ull c) {
    ull d;
    asm("fma.rn.f32x2 %0, %1, %2, %3;" : "=l"(d) : "l"(a), "l"(b), "l"(c));
    return d;
}
__device__ __forceinline__ ull pack2(float lo, float hi) {
    ull r;
    asm("mov.b64 %0, {%1, %2};" : "=l"(r) : "f"(lo), "f"(hi));
    return r;
}
__device__ __forceinline__ float2 unpack2(ull v) {
    float2 r;
    asm("mov.b64 {%0, %1}, %2;" : "=f"(r.x), "=f"(r.y) : "l"(v));
    return r;
}

// ---------------- 1) grouped ConvTranspose2d(2,2,k=4,s=2,p=1,groups=2) ----------------
__global__ void k_upsample(const float* __restrict__ flow, const float* __restrict__ up_w,
                           float* __restrict__ out) {
    int idx = blockIdx.x * blockDim.x + threadIdx.x;
    if (idx >= BB*2*HW) return;
    int x = idx & 127;
    int y = (idx >> 7) & 127;
    int g = (idx >> 14) & 1;
    int b = idx >> 15;
    const float* fin = flow + (b*2 + g) * 64 * 64;
    const float* wg  = up_w + g * 16;
    float acc = 0.f;
    #pragma unroll
    for (int ky = 0; ky < 4; ky++) {
        int t = y + 1 - ky;
        if (t & 1) continue;
        int i = t >> 1;
        if ((unsigned)i >= 64u) continue;
        #pragma unroll
        for (int kx = 0; kx < 4; kx++) {
            int s = x + 1 - kx;
            if (s & 1) continue;
            int j = s >> 1;
            if ((unsigned)j >= 64u) continue;
            acc += fin[i*64 + j] * wg[ky*4 + kx];
        }
    }
    out[idx] = acc;
}

// ---------------- 2) warp feature2 (bilinear, reflect border, align_corners) -------------
__device__ __forceinline__ float reflectf(float v, float n) {
    float t = fmodf(fabsf(v), 2.0f * n);
    return n - fabsf(t - n);
}

__global__ void k_warp(const float* __restrict__ f2, const float* __restrict__ fu,
                       float* __restrict__ f2w) {
    int x = threadIdx.x;
    int y = blockIdx.x;
    int b = blockIdx.y;
    int c0 = blockIdx.z * 32;

    const float* fub = fu + (size_t)b*2*HW;
    float u0 = fub[y*WW + x];
    float u1 = fub[HW + y*WW + x];

    float fx = reflectf((float)x + 0.05f*u1, 127.f);
    float fy = reflectf((float)y + 0.05f*u0, 127.f);

    float x0f = floorf(fx), y0f = floorf(fy);
    float wx = fx - x0f, wy = fy - y0f;
    int x0 = min(max((int)x0f, 0), 127);
    int x1 = min(x0 + 1, 127);
    int y0 = min(max((int)y0f, 0), 127);
    int y1 = min(y0 + 1, 127);
    float w00 = (1.f-wx)*(1.f-wy), w01 = wx*(1.f-wy);
    float w10 = (1.f-wx)*wy,       w11 = wx*wy;

    int o00 = y0*WW + x0, o01 = y0*WW + x1, o10 = y1*WW + x0, o11 = y1*WW + x1;
    const float* fb = f2  + (size_t)b*128*HW;
    float*       ob = f2w + (size_t)b*128*HW;
    int po = y*WW + x;
    #pragma unroll 4
    for (int c = c0; c < c0 + 32; c++) {
        const float* fc = fb + (size_t)c*HW;
        ob[(size_t)c*HW + po] = w00*fc[o00] + w01*fc[o01] + w10*fc[o10] + w11*fc[o11];
    }
}

// ---------------- 3) cost volume: packed pixel pairs, 16-ch staging ----------------
// Block (8,16)=128 threads, tile 16x16 px (2 px/thread). acc: 49 packed pairs.
__global__ void __launch_bounds__(128) k_corr(const float* __restrict__ f1,
                                              const float* __restrict__ f2w,
                                              float* __restrict__ corr) {
    constexpr int CH = 16;
    __shared__ __align__(16) float s2[CH][22][24];

    int tx = threadIdx.x, ty = threadIdx.y;
    int tid = ty*8 + tx;
    int bx = blockIdx.x*16, by = blockIdx.y*16, b = blockIdx.z;
    int x = bx + 2*tx, y = by + ty;

    // precompute fill slots (484 elems / 128 threads -> 4 slots)
    int soff[4], goff[4];
    bool inr[4], val[4];
    #pragma unroll
    for (int s = 0; s < 4; s++) {
        int i = tid + s*128;
        int r = i / 22, c = i - r*22;
        int gy = by - 3 + r, gx = bx - 3 + c;
        inr[s] = (i < 484);
        val[s] = inr[s] && (unsigned)gy < (unsigned)HH && (unsigned)gx < (unsigned)WW;
        soff[s] = r*24 + c;
        goff[s] = val[s] ? gy*WW + gx : 0;
    }

    ull acc[49];
    #pragma unroll
    for (int d = 0; d < 49; d++) acc[d] = 0ull;

    const float* f1p = f1 + (size_t)b*128*HW + y*WW + x;
    const float* f2b = f2w + (size_t)b*128*HW;

    #pragma unroll 1
    for (int c0 = 0; c0 < 128; c0 += CH) {
        __syncthreads();
        #pragma unroll 1
        for (int ci = 0; ci < CH; ci++) {
            const float* cp = f2b + (size_t)(c0 + ci)*HW;
            float* sp = &s2[ci][0][0];
            #pragma unroll
            for (int s = 0; s < 4; s++)
                if (inr[s]) sp[soff[s]] = val[s] ? __ldg(cp + goff[s]) : 0.f;
        }
        __syncthreads();
        #pragma unroll 1
        for (int ci = 0; ci < CH; ci++) {
            ull a = *(const ull*)(f1p + (size_t)(c0 + ci)*HW);
            #pragma unroll
            for (int dy = 0; dy < 7; dy++) {
                const ull* row = (const ull*)&s2[ci][ty + dy][0];
                ull L0 = row[tx], L1 = row[tx+1], L2 = row[tx+2], L3 = row[tx+3];
                float2 b0 = unpack2(L0), b1 = unpack2(L1), b2 = unpack2(L2), b3 = unpack2(L3);
                ull T1 = pack2(b0.y, b1.x);
                ull T3 = pack2(b1.y, b2.x);
                ull T5 = pack2(b2.y, b3.x);
                acc[dy*7+0] = ffma2(a, L0, acc[dy*7+0]);
                acc[dy*7+1] = ffma2(a, T1, acc[dy*7+1]);
                acc[dy*7+2] = ffma2(a, L1, acc[dy*7+2]);
                acc[dy*7+3] = ffma2(a, T3, acc[dy*7+3]);
                acc[dy*7+4] = ffma2(a, L2, acc[dy*7+4]);
                acc[dy*7+5] = ffma2(a, T5, acc[dy*7+5]);
                acc[dy*7+6] = ffma2(a, L3, acc[dy*7+6]);
            }
        }
    }

    float* cb = corr + (size_t)b*49*HW + y*WW + x;
    #pragma unroll
    for (int d = 0; d < 49; d++) {
        float2 v = unpack2(acc[d]);
        v.x *= (1.f/128.f); v.y *= (1.f/128.f);
        v.x = (v.x >= 0.f) ? v.x : 0.01f*v.x;
        v.y = (v.y >= 0.f) ? v.y : 0.01f*v.y;
        *(float2*)(cb + (size_t)d*HW) = v;
    }
}

// ---------------- 4) direct 3x3 conv: 4 px/thread, CH-channel staging ----------------
// Block (16,16), tile 64x16 px. Each thread: 2 packed pixel pairs x KOC out channels.
template<int CIN, int COUT, int KOC, int CH>
__global__ void __launch_bounds__(256, 2) k_conv(
    const float* __restrict__ in, const float* __restrict__ w,
    const float* __restrict__ bias, float* __restrict__ out,
    float slope, const float* __restrict__ addsrc)
{
    static_assert(CIN % CH == 0, "");
    constexpr int TROW = 18, TCOL = 68;
    constexpr int TFILL = 18*66;
    constexpr int WCNT = CH*KOC*9;
    constexpr int WSLOT = (WCNT + 255)/256;

    __shared__ __align__(16) float s_in[CH][TROW][TCOL];
    __shared__ __align__(16) ull s_w[WCNT];

    int tx = threadIdx.x, ty = threadIdx.y;
    int tid = ty*16 + tx;
    int bx = blockIdx.x*64, by = blockIdx.y*16;
    int ocg = blockIdx.z % (COUT/KOC);
    int b   = blockIdx.z / (COUT/KOC);
    int oc0 = ocg * KOC;

    // precompute tile-fill slots (1188 elems / 256 threads -> 5 slots)
    int soff[5], goff[5];
    bool inr[5], val[5];
    #pragma unroll
    for (int s = 0; s < 5; s++) {
        int i = tid + s*256;
        int r = i / 66, c = i - r*66;
        int gy = by - 1 + r, gx = bx - 1 + c;
        inr[s] = (i < TFILL);
        val[s] = inr[s] && (unsigned)gy < (unsigned)HH && (unsigned)gx < (unsigned)WW;
        soff[s] = r*TCOL + c;
        goff[s] = val[s] ? gy*WW + gx : 0;
    }
    // precompute weight-fill slots
    int wA[WSLOT];
    bool winr[WSLOT];
    #pragma unroll
    for (int s = 0; s < WSLOT; s++) {
        int i = tid + s*256;
        winr[s] = (i < WCNT);
        int ci = i / (KOC*9), rem = i % (KOC*9);
        int o = rem / 9, k = rem % 9;
        wA[s] = (o*CIN + ci)*9 + k;
    }

    const float* inb = in + (size_t)b*CIN*HW;
    float* sbase = &s_in[0][0][0];

    ull accA[KOC], accB[KOC];
    #pragma unroll
    for (int o = 0; o < KOC; o++) { accA[o] = 0ull; accB[o] = 0ull; }

    int wbase = oc0*CIN*9;

    #pragma unroll 1
    for (int c0 = 0; c0 < CIN; c0 += CH) {
        __syncthreads();
        #pragma unroll 1
        for (int ci = 0; ci < CH; ci++) {
            const float* cp = inb + (size_t)(c0 + ci)*HW;
            float* sp = sbase + ci*(TROW*TCOL);
            #pragma unroll
            for (int s = 0; s < 5; s++)
                if (inr[s]) sp[soff[s]] = val[s] ? __ldg(cp + goff[s]) : 0.f;
        }
        #pragma unroll
        for (int s = 0; s < WSLOT; s++) {
            if (winr[s]) {
                float wv = __ldg(w + wbase + c0*9 + wA[s]);
                s_w[tid + s*256] = pack2(wv, wv);
            }
        }
        __syncthreads();

        #pragma unroll 1
        for (int ci = 0; ci < CH; ci++) {
            const ull* wp = s_w + ci*(KOC*9);
            const float* tb = sbase + ci*(TROW*TCOL) + ty*TCOL;
            #pragma unroll
            for (int ky = 0; ky < 3; ky++) {
                const ull* row = (const ull*)(tb + ky*TCOL);
                ull L0 = row[2*tx], L1 = row[2*tx+1], L2 = row[2*tx+2];
                float2 a0 = unpack2(L0), a1 = unpack2(L1), a2 = unpack2(L2);
                ull T1 = pack2(a0.y, a1.x);
                ull T3 = pack2(a1.y, a2.x);
                #pragma unroll
                for (int o = 0; o < KOC; o++) {
                    ull w0 = wp[o*9 + ky*3 + 0];
                    ull w1 = wp[o*9 + ky*3 + 1];
                    ull w2 = wp[o*9 + ky*3 + 2];
                    accA[o] = ffma2(L0, w0, accA[o]);
                    accA[o] = ffma2(T1, w1, accA[o]);
                    accA[o] = ffma2(L1, w2, accA[o]);
                    accB[o] = ffma2(L1, w0, accB[o]);
                    accB[o] = ffma2(T3, w1, accB[o]);
                    accB[o] = ffma2(L2, w2, accB[o]);
                }
            }
        }
    }

    int y = by + ty;
    int x = bx + 4*tx;
    #pragma unroll
    for (int o = 0; o < KOC; o++) {
        float2 vA = unpack2(accA[o]);
        float2 vB = unpack2(accB[o]);
        float bv = bias[oc0 + o];
        vA.x += bv; vA.y += bv; vB.x += bv; vB.y += bv;
        vA.x = (vA.x >= 0.f) ? vA.x : slope*vA.x;
        vA.y = (vA.y >= 0.f) ? vA.y : slope*vA.y;
        vB.x = (vB.x >= 0.f) ? vB.x : slope*vB.x;
        vB.y = (vB.y >= 0.f) ? vB.y : slope*vB.y;
        size_t off = ((size_t)(b*COUT + oc0 + o))*HW + y*WW + x;
        if (addsrc) {
            float2 r0 = *(const float2*)(addsrc + off);
            float2 r1 = *(const float2*)(addsrc + off + 2);
            vA.x += r0.x; vA.y += r0.y; vB.x += r1.x; vB.y += r1.y;
        }
        *(float2*)(out + off)     = vA;
        *(float2*)(out + off + 2) = vB;
    }
}

// ---------------- launch ----------------
extern "C" void kernel_launch(void* const* d_in, const int* in_sizes, int n_in,
                              void* d_out, int out_size) {
    const float* feature1 = (const float*)d_in[0];
    const float* feature2 = (const float*)d_in[1];
    const float* flow     = (const float*)d_in[2];
    const float* up_w     = (const float*)d_in[3];
    const float* w1 = (const float*)d_in[4];  const float* b1 = (const float*)d_in[5];
    const float* w2 = (const float*)d_in[6];  const float* b2 = (const float*)d_in[7];
    const float* w3 = (const float*)d_in[8];  const float* b3 = (const float*)d_in[9];
    const float* w4 = (const float*)d_in[10]; const float* b4 = (const float*)d_in[11];
    float* out = (float*)d_out;

    float *p_flow_up, *p_f2w, *p_corr, *p_h1, *p_h2, *p_h3;
    cudaGetSymbolAddress((void**)&p_flow_up, g_flow_up);
    cudaGetSymbolAddress((void**)&p_f2w,     g_f2w);
    cudaGetSymbolAddress((void**)&p_corr,    g_corr);
    cudaGetSymbolAddress((void**)&p_h1,      g_h1);
    cudaGetSymbolAddress((void**)&p_h2,      g_h2);
    cudaGetSymbolAddress((void**)&p_h3,      g_h3);

    k_upsample<<<(BB*2*HW + 255)/256, 256>>>(flow, up_w, p_flow_up);
    k_warp<<<dim3(HH, BB, 4), 128>>>(feature2, p_flow_up, p_f2w);
    k_corr<<<dim3(8, 8, BB), dim3(8, 16)>>>(feature1, p_f2w, p_corr);
    k_conv<49, 128, 8, 7><<<dim3(2, 8, BB*16), dim3(16, 16)>>>(p_corr, w1, b1, p_h1, 0.1f, nullptr);
    k_conv<128, 64, 8, 8><<<dim3(2, 8, BB*8),  dim3(16, 16)>>>(p_h1,  w2, b2, p_h2, 0.1f, nullptr);
    k_conv<64, 32, 8, 8><<<dim3(2, 8, BB*4),  dim3(16, 16)>>>(p_h2,  w3, b3, p_h3, 0.1f, nullptr);
    k_conv<32, 2, 2, 8><<<dim3(2, 8, BB),     dim3(16, 16)>>>(p_h3,  w4, b4, out, 1.0f, p_flow_up);
}